// round 2
// baseline (speedup 1.0000x reference)
#include <cuda_runtime.h>
#include <math.h>

#define Bq   32
#define Lq   512
#define Hq   512
#define DIN  832
#define G3   1536
#define BL   (Bq*Lq)          // 16384

// ------------------------- scratch (device globals) -------------------------
__device__ __align__(16) float g_X[2][(size_t)BL * DIN];      // 109 MB
__device__ __align__(16) float g_gi[4][(size_t)BL * G3];      // 402 MB
__device__ __align__(16) float g_h[4][2][Hq * Bq];            // ping-pong hidden [k][b]
__device__ __align__(16) float g_enc[2][(size_t)BL * 1024];   // 134 MB
__device__ __align__(16) float g_sim[(size_t)Bq * Lq * Lq];   // 33.5 MB
__device__ __align__(16) float g_max1[BL], g_rel1[BL], g_max2[BL], g_rel2[BL];
__device__ __align__(16) float g_feat[Bq * 768];
__device__ unsigned g_ctr[4];

// ------------------------- init (reset recurrence state) -------------------------
__global__ void k_init() {
    int i = blockIdx.x * blockDim.x + threadIdx.x;
    if (i < 4 * 2 * Hq * Bq) (&g_h[0][0][0])[i] = 0.f;
    if (i < 4) g_ctr[i] = 0u;
}

// ------------------------- embedding concat -------------------------
__global__ void k_embed(const int* __restrict__ w1, const int* __restrict__ w2,
                        const int* __restrict__ p1, const int* __restrict__ p2,
                        const int* __restrict__ tb1, const int* __restrict__ te1,
                        const int* __restrict__ tb2, const int* __restrict__ te2,
                        const float* __restrict__ ew, const float* __restrict__ ep,
                        const float* __restrict__ pe) {
    int tok  = blockIdx.x;               // b*L + t
    int side = blockIdx.y;
    int t    = tok & (Lq - 1);
    const int* w  = side ? w2  : w1;
    const int* pp = side ? p2  : p1;
    const int* tb = side ? tb2 : tb1;
    const int* te = side ? te2 : te1;
    int wi = w[tok], pi = pp[tok], bi = tb[tok], ei = te[tok];
    float* dst = g_X[side] + (size_t)tok * DIN;
    const float* s0 = ew + (size_t)wi * 256;
    const float* s1 = ep + (size_t)pi * 256;
    for (int i = threadIdx.x; i < 256; i += 128) {
        dst[i]       = s0[i];
        dst[256 + i] = s1[i];
    }
    const float* q0 = pe + t * 64;
    const float* q1 = pe + bi * 64;
    const float* q2 = pe + ei * 64;
    const float* q3 = pe + (ei - t) * 64;
    const float* q4 = pe + (t - bi) * 64;
    for (int i = threadIdx.x; i < 64; i += 128) {
        dst[512 + i] = q0[i];
        dst[576 + i] = q1[i];
        dst[640 + i] = q2[i];
        dst[704 + i] = q3[i];
        dst[768 + i] = q4[i];
    }
}

// ------------------------- SGEMM: C[M,N] = A[M,K] * W[N,K]^T (+bias) -------------------------
// mode 0: gi GEMM, z in 0..3 -> (side=z>>1, dir=z&1); A rows gathered reversed when dir=1.
// mode 1: sim GEMM, z = batch 0..31, A=enc1[z], W=enc2[z], C=sim[z].
#define BM 128
#define BN 128
#define BKG 8
#define SLD 132

__global__ void __launch_bounds__(256, 2) k_gemm(
    int mode, const float* __restrict__ wih, const float* __restrict__ bih,
    const int* __restrict__ len1, const int* __restrict__ len2,
    int M, int N, int K)
{
    __shared__ float As[BKG * SLD];
    __shared__ float Bs[BKG * SLD];
    const float *A, *W, *bias;
    float* C;
    const int* lens = 0;
    int rev = 0;
    int z = blockIdx.z;
    if (mode == 0) {
        int side = z >> 1, dir = z & 1;
        A    = g_X[side];
        W    = wih + (size_t)dir * G3 * DIN;
        bias = bih + dir * G3;
        C    = g_gi[z];
        lens = side ? len2 : len1;
        rev  = dir;
    } else {
        A    = g_enc[0] + (size_t)z * Lq * 1024;
        W    = g_enc[1] + (size_t)z * Lq * 1024;
        bias = 0;
        C    = g_sim + (size_t)z * Lq * Lq;
    }
    int tid  = threadIdx.x;
    int m0   = blockIdx.y * BM, n0 = blockIdx.x * BN;
    int lrow = tid >> 1;
    int kq   = (tid & 1) * 4;
    int arow = m0 + lrow;
    if (rev) {
        int b = arow >> 9, t = arow & 511;
        int Lb = lens[b];
        arow = (b << 9) + ((t < Lb) ? (Lb - 1 - t) : t);
    }
    const float* ap = A + (size_t)arow * K + kq;
    const float* bp = W + (size_t)(n0 + lrow) * K + kq;
    int tx = tid & 15, ty = tid >> 4;

    float acc[8][8];
#pragma unroll
    for (int i = 0; i < 8; i++)
#pragma unroll
        for (int j = 0; j < 8; j++) acc[i][j] = 0.f;

    for (int k0 = 0; k0 < K; k0 += BKG) {
        float4 av = *(const float4*)(ap + k0);
        float4 bv = *(const float4*)(bp + k0);
        __syncthreads();
        As[(kq + 0) * SLD + lrow] = av.x;
        As[(kq + 1) * SLD + lrow] = av.y;
        As[(kq + 2) * SLD + lrow] = av.z;
        As[(kq + 3) * SLD + lrow] = av.w;
        Bs[(kq + 0) * SLD + lrow] = bv.x;
        Bs[(kq + 1) * SLD + lrow] = bv.y;
        Bs[(kq + 2) * SLD + lrow] = bv.z;
        Bs[(kq + 3) * SLD + lrow] = bv.w;
        __syncthreads();
#pragma unroll
        for (int kk = 0; kk < BKG; kk++) {
            float a[8], b2[8];
#pragma unroll
            for (int i = 0; i < 8; i++) a[i]  = As[kk * SLD + ty + 16 * i];
#pragma unroll
            for (int j = 0; j < 8; j++) b2[j] = Bs[kk * SLD + tx + 16 * j];
#pragma unroll
            for (int i = 0; i < 8; i++)
#pragma unroll
                for (int j = 0; j < 8; j++) acc[i][j] += a[i] * b2[j];
        }
    }
#pragma unroll
    for (int i = 0; i < 8; i++) {
        int m = m0 + ty + 16 * i;
#pragma unroll
        for (int j = 0; j < 8; j++) {
            int n = n0 + tx + 16 * j;
            float v = acc[i][j];
            if (bias) v += bias[n];
            C[(size_t)m * N + n] = v;
        }
    }
}

// ------------------------- persistent GRU scan -------------------------
// 4 chains x 32 blocks. Block owns 16 hidden units (all 3 gates = 48 Whh rows in smem).
// h ping-pongs through global [k][b] layout with a per-chain atomic step barrier.
#define GRU_SMEM ((48 * 512 + 512 * 33 + 48 * 33) * 4)

__global__ void __launch_bounds__(256, 1) k_gru(
    const float* __restrict__ whh, const float* __restrict__ bhh,
    const int* __restrict__ len1, const int* __restrict__ len2)
{
    extern __shared__ float sm[];
    float* Ws  = sm;                         // [48][512]
    float* hs  = sm + 48 * 512;              // [512][33] (transposed, padded)
    float* ghs = hs + 512 * 33;              // [48][33]

    int chain = blockIdx.x >> 5;
    int blk   = blockIdx.x & 31;
    int side  = chain >> 1, dir = chain & 1;
    int j0    = blk * 16;
    int tid   = threadIdx.x;
    const int* lens = side ? len2 : len1;
    const float* gi = g_gi[chain];
    float* enc = g_enc[side];

    // load Whh slice: rr = g*16+u  <->  whh row dir*1536 + g*512 + j0 + u
    for (int i = tid; i < 48 * 512; i += 256) {
        int rr = i >> 9, k = i & 511;
        int g = rr >> 4, u = rr & 15;
        Ws[rr * 512 + k] = whh[((size_t)dir * G3 + g * 512 + j0 + u) * 512 + k];
    }

    // compute-phase lane mapping
    int w  = tid >> 5, l = tid & 31;
    int q  = l >> 2, ks = l & 3;
    int rr0 = w * 6;         // 6 rows of the 48
    int b0  = q * 4;         // 4 batches of the 32

    // gate-phase per-thread constants (handles idx = tid and tid+256)
    int gb  = tid & 31;
    int u0  = tid >> 5;      // 0..7
    int u1  = u0 + 8;        // 8..15
    int lenb = lens[gb];
    float bhr0 = bhh[dir * G3 +        j0 + u0];
    float bhz0 = bhh[dir * G3 +  512 + j0 + u0];
    float bhn0 = bhh[dir * G3 + 1024 + j0 + u0];
    float bhr1 = bhh[dir * G3 +        j0 + u1];
    float bhz1 = bhh[dir * G3 +  512 + j0 + u1];
    float bhn1 = bhh[dir * G3 + 1024 + j0 + u1];

    unsigned tgt = 0;
    for (int t = 0; t < Lq; ++t) {
        int p = t & 1;
        // stage h (global [k*32+b] -> smem [k*33+b])
        const float* hsrc = g_h[chain][p];
        for (int i = tid * 4; i < Hq * Bq; i += 1024) {
            float4 v = __ldcg((const float4*)(hsrc + i));
            int k = i >> 5, b = i & 31;
            float* d = hs + k * 33 + b;
            d[0] = v.x; d[1] = v.y; d[2] = v.z; d[3] = v.w;
        }
        __syncthreads();

        // gh partials: 6 rows x 4 batches per lane, K split 4-ways interleaved (k = 4*kk + ks)
        float acc[6][4];
#pragma unroll
        for (int y = 0; y < 6; y++)
#pragma unroll
            for (int x = 0; x < 4; x++) acc[y][x] = 0.f;
        {
            const float* hp = hs + ks * 33 + b0;
            const float* wp = Ws + rr0 * 512 + ks;
#pragma unroll 4
            for (int kk = 0; kk < 128; ++kk) {
                float h0 = hp[0], h1 = hp[1], h2 = hp[2], h3 = hp[3];
#pragma unroll
                for (int y = 0; y < 6; y++) {
                    float wv = wp[y * 512];
                    acc[y][0] += wv * h0;
                    acc[y][1] += wv * h1;
                    acc[y][2] += wv * h2;
                    acc[y][3] += wv * h3;
                }
                hp += 132; wp += 4;
            }
        }
        // reduce over the 4 k-slices (lanes ks=0..3 within each quad)
#pragma unroll
        for (int y = 0; y < 6; y++)
#pragma unroll
            for (int x = 0; x < 4; x++) {
                float v = acc[y][x];
                v += __shfl_xor_sync(0xffffffffu, v, 1);
                v += __shfl_xor_sync(0xffffffffu, v, 2);
                acc[y][x] = v;
            }
        if (ks == 0) {
#pragma unroll
            for (int y = 0; y < 6; y++)
#pragma unroll
                for (int x = 0; x < 4; x++)
                    ghs[(rr0 + y) * 33 + b0 + x] = acc[y][x];
        }
        __syncthreads();

        // gates + state update (2 units per thread)
        bool valid = t < lenb;
        int tout = dir ? (valid ? lenb - 1 - t : t) : t;
        size_t tok = (size_t)((gb << 9) | t);
        size_t otok = (size_t)((gb << 9) | tout);
        const float* gp = gi + tok * G3 + j0;
        float* hdst = g_h[chain][p ^ 1];

        {
            float ir = gp[u0], iz = gp[512 + u0], inn = gp[1024 + u0];
            float hr = ghs[u0 * 33 + gb] + bhr0;
            float hz = ghs[(16 + u0) * 33 + gb] + bhz0;
            float hn = ghs[(32 + u0) * 33 + gb] + bhn0;
            float r  = 1.f / (1.f + expf(-(ir + hr)));
            float zz = 1.f / (1.f + expf(-(iz + hz)));
            float nn = tanhf(inn + r * hn);
            float hprev = hs[(j0 + u0) * 33 + gb];
            float hnew  = (1.f - zz) * nn + zz * hprev;
            hdst[((j0 + u0) << 5) + gb] = valid ? hnew : hprev;
            enc[otok * 1024 + (dir << 9) + j0 + u0] = valid ? hnew : 0.f;
        }
        {
            float ir = gp[u1], iz = gp[512 + u1], inn = gp[1024 + u1];
            float hr = ghs[u1 * 33 + gb] + bhr1;
            float hz = ghs[(16 + u1) * 33 + gb] + bhz1;
            float hn = ghs[(32 + u1) * 33 + gb] + bhn1;
            float r  = 1.f / (1.f + expf(-(ir + hr)));
            float zz = 1.f / (1.f + expf(-(iz + hz)));
            float nn = tanhf(inn + r * hn);
            float hprev = hs[(j0 + u1) * 33 + gb];
            float hnew  = (1.f - zz) * nn + zz * hprev;
            hdst[((j0 + u1) << 5) + gb] = valid ? hnew : hprev;
            enc[otok * 1024 + (dir << 9) + j0 + u1] = valid ? hnew : 0.f;
        }

        // device-scope step barrier (per chain)
        __threadfence();
        __syncthreads();
        tgt += 32;
        if (tid == 0) {
            atomicAdd(&g_ctr[chain], 1u);
            while (*(volatile unsigned*)&g_ctr[chain] < tgt) { }
        }
        __syncthreads();
    }
}

// ------------------------- row normalize enc -------------------------
__global__ void k_norm() {
    float* row = g_enc[blockIdx.y] + (size_t)blockIdx.x * 1024;
    int tid = threadIdx.x;
    float ss = 0.f;
    for (int i = tid; i < 1024; i += 128) { float v = row[i]; ss += v * v; }
    __shared__ float red[4];
    for (int o = 16; o; o >>= 1) ss += __shfl_down_sync(0xffffffffu, ss, o);
    if ((tid & 31) == 0) red[tid >> 5] = ss;
    __syncthreads();
    float tot = red[0] + red[1] + red[2] + red[3];
    float sc = tot > 0.f ? 1.f / sqrtf(tot) : 0.f;
    for (int i = tid; i < 1024; i += 128) row[i] *= sc;
}

// ------------------------- row / col max+argmax (first-index ties) -------------------------
__global__ void k_rowmax() {
    int row = blockIdx.x * 8 + (threadIdx.x >> 5);     // global row b*512+i
    int l = threadIdx.x & 31;
    const float* s = g_sim + (size_t)row * Lq;
    float bv = -1e30f; int bi = 0;
    for (int j = l; j < Lq; j += 32) {
        float v = s[j];
        if (v > bv) { bv = v; bi = j; }
    }
    for (int o = 16; o; o >>= 1) {
        float ov = __shfl_down_sync(0xffffffffu, bv, o);
        int   oi = __shfl_down_sync(0xffffffffu, bi, o);
        if (ov > bv || (ov == bv && oi < bi)) { bv = ov; bi = oi; }
    }
    if (l == 0) {
        int i = row & 511;
        g_max1[row] = bv;
        g_rel1[row] = (float)(i - bi);
    }
}

__global__ void k_colmax() {
    int id = blockIdx.x * blockDim.x + threadIdx.x;    // b*512+j
    int b = id >> 9, j = id & 511;
    const float* s = g_sim + ((size_t)b * Lq) * Lq + j;
    float bv = -1e30f; int bi = 0;
    for (int i = 0; i < Lq; ++i) {
        float v = s[(size_t)i * Lq];
        if (v > bv) { bv = v; bi = i; }
    }
    g_max2[id] = bv;
    g_rel2[id] = (float)(j - bi);
}

// ------------------------- conv branches + maxpool -------------------------
__global__ void k_head(const float* __restrict__ w2p, const float* __restrict__ w3p,
                       const float* __restrict__ w4p, const float* __restrict__ cb,
                       const float* __restrict__ bg, const float* __restrict__ bb,
                       const float* __restrict__ bm, const float* __restrict__ bvv)
{
    int b = blockIdx.x, br = blockIdx.y;
    __shared__ float x0[512], x1[512];
    const float* ms = br ? g_max2 : g_max1;
    const float* rl = br ? g_rel2 : g_rel1;
    for (int i = threadIdx.x; i < 512; i += 128) {
        x0[i] = ms[b * 512 + i];
        x1[i] = rl[b * 512 + i];
    }
    __syncthreads();
    int c = threadIdx.x;
    float* fout = g_feat + b * 768 + br * 384;
    const float* wp[3] = { w2p, w3p, w4p };
    const int kss[3] = { 2, 3, 4 };
    for (int ki = 0; ki < 3; ++ki) {
        int ks = kss[ki];
        float w0[4], w1[4];
        for (int kk = 0; kk < 4; kk++) {
            w0[kk] = kk < ks ? wp[ki][(c * 2 + 0) * ks + kk] : 0.f;
            w1[kk] = kk < ks ? wp[ki][(c * 2 + 1) * ks + kk] : 0.f;
        }
        float s  = bg[ki * 128 + c] / sqrtf(bvv[ki * 128 + c] + 1e-5f);
        float sh = bb[ki * 128 + c] - bm[ki * 128 + c] * s;
        float bias = cb[ki * 128 + c];
        float best = 0.f;
        for (int p = 0; p <= 512 - ks; ++p) {
            float acc = bias;
#pragma unroll
            for (int kk = 0; kk < 4; kk++)
                if (kk < ks) acc += w0[kk] * x0[p + kk] + w1[kk] * x1[p + kk];
            float y = fmaxf(acc * s + sh, 0.f);
            best = fmaxf(best, y);
        }
        fout[ki * 128 + c] = best;
    }
}

// ------------------------- FC + softmax -------------------------
__global__ void k_fc(const float* __restrict__ fcw, const float* __restrict__ fcb,
                     float* __restrict__ out)
{
    int id = threadIdx.x;          // 64 threads: (b, cls)
    int b = id >> 1, cls = id & 1;
    float acc = fcb[cls];
    const float* f = g_feat + b * 768;
    const float* wrow = fcw + cls * 768;
    for (int k = 0; k < 768; ++k) acc += f[k] * wrow[k];
    float other = __shfl_xor_sync(0xffffffffu, acc, 1);
    float m = fmaxf(acc, other);
    float e = expf(acc - m);
    float ssum = e + expf(other - m);
    out[id] = e / ssum;
}

// ------------------------- launch -------------------------
extern "C" void kernel_launch(void* const* d_in, const int* in_sizes, int n_in,
                              void* d_out, int out_size)
{
    const int* w1  = (const int*)d_in[0];
    const int* w2  = (const int*)d_in[1];
    const int* p1  = (const int*)d_in[2];
    const int* p2  = (const int*)d_in[3];
    const int* ln1 = (const int*)d_in[4];
    const int* ln2 = (const int*)d_in[5];
    const int* tb1 = (const int*)d_in[6];
    const int* te1 = (const int*)d_in[7];
    const int* tb2 = (const int*)d_in[8];
    const int* te2 = (const int*)d_in[9];
    const float* ew   = (const float*)d_in[10];
    const float* ep   = (const float*)d_in[11];
    const float* pe   = (const float*)d_in[12];
    const float* wih  = (const float*)d_in[13];
    const float* whh  = (const float*)d_in[14];
    const float* bih  = (const float*)d_in[15];
    const float* bhh  = (const float*)d_in[16];
    const float* cw0  = (const float*)d_in[17];
    const float* cw1  = (const float*)d_in[18];
    const float* cw2  = (const float*)d_in[19];
    const float* cb   = (const float*)d_in[20];
    const float* bg   = (const float*)d_in[21];
    const float* bb   = (const float*)d_in[22];
    const float* bm   = (const float*)d_in[23];
    const float* bv   = (const float*)d_in[24];
    const float* fcw  = (const float*)d_in[25];
    const float* fcb  = (const float*)d_in[26];
    float* out = (float*)d_out;

    cudaFuncSetAttribute(k_gru, cudaFuncAttributeMaxDynamicSharedMemorySize, GRU_SMEM);

    k_init<<<512, 256>>>();
    k_embed<<<dim3(BL, 2), 128>>>(w1, w2, p1, p2, tb1, te1, tb2, te2, ew, ep, pe);
    k_gemm<<<dim3(G3 / BN, BL / BM, 4), 256>>>(0, wih, bih, ln1, ln2, BL, G3, DIN);
    k_gru<<<128, 256, GRU_SMEM>>>(whh, bhh, ln1, ln2);
    k_norm<<<dim3(BL, 2), 128>>>();
    k_gemm<<<dim3(Lq / BN, Lq / BM, Bq), 256>>>(1, 0, 0, 0, 0, Lq, Lq, 1024);
    k_rowmax<<<BL / 8, 256>>>();
    k_colmax<<<BL / 256, 256>>>();
    k_head<<<dim3(Bq, 2), 128>>>(cw0, cw1, cw2, cb, bg, bb, bm, bv);
    k_fc<<<1, 64>>>(fcw, fcb, out);
}

// round 3
// speedup vs baseline: 1.3605x; 1.3605x over previous
#include <cuda_runtime.h>
#include <math.h>

#define Bq   32
#define Lq   512
#define Hq   512
#define DIN  832
#define G3   1536
#define BL   (Bq*Lq)          // 16384

// ------------------------- scratch (device globals) -------------------------
__device__ __align__(16) float g_X[2][(size_t)BL * DIN];      // 109 MB
__device__ __align__(16) float g_gi[4][(size_t)BL * G3];      // 402 MB
__device__ __align__(16) float g_h[4][2][Hq * Bq];            // ping-pong hidden [k][b]
__device__ __align__(16) float g_enc[2][(size_t)BL * 1024];   // 134 MB
__device__ __align__(16) float g_sim[(size_t)Bq * Lq * Lq];   // 33.5 MB
__device__ __align__(16) float g_max1[BL], g_rel1[BL], g_max2[BL], g_rel2[BL];
__device__ __align__(16) float g_feat[Bq * 768];
__device__ unsigned g_ctr[4];

// ------------------------- init (reset recurrence state) -------------------------
__global__ void k_init() {
    int i = blockIdx.x * blockDim.x + threadIdx.x;
    if (i < 4 * 2 * Hq * Bq) (&g_h[0][0][0])[i] = 0.f;
    if (i < 4) g_ctr[i] = 0u;
}

// ------------------------- embedding concat -------------------------
__global__ void k_embed(const int* __restrict__ w1, const int* __restrict__ w2,
                        const int* __restrict__ p1, const int* __restrict__ p2,
                        const int* __restrict__ tb1, const int* __restrict__ te1,
                        const int* __restrict__ tb2, const int* __restrict__ te2,
                        const float* __restrict__ ew, const float* __restrict__ ep,
                        const float* __restrict__ pe) {
    int tok  = blockIdx.x;               // b*L + t
    int side = blockIdx.y;
    int t    = tok & (Lq - 1);
    const int* w  = side ? w2  : w1;
    const int* pp = side ? p2  : p1;
    const int* tb = side ? tb2 : tb1;
    const int* te = side ? te2 : te1;
    int wi = w[tok], pi = pp[tok], bi = tb[tok], ei = te[tok];
    float* dst = g_X[side] + (size_t)tok * DIN;
    const float* s0 = ew + (size_t)wi * 256;
    const float* s1 = ep + (size_t)pi * 256;
    for (int i = threadIdx.x; i < 256; i += 128) {
        dst[i]       = s0[i];
        dst[256 + i] = s1[i];
    }
    const float* q0 = pe + t * 64;
    const float* q1 = pe + bi * 64;
    const float* q2 = pe + ei * 64;
    const float* q3 = pe + (ei - t) * 64;
    const float* q4 = pe + (t - bi) * 64;
    for (int i = threadIdx.x; i < 64; i += 128) {
        dst[512 + i] = q0[i];
        dst[576 + i] = q1[i];
        dst[640 + i] = q2[i];
        dst[704 + i] = q3[i];
        dst[768 + i] = q4[i];
    }
}

// ------------------------- tf32 tensor-core GEMM for gi -------------------------
// C[16384,1536] = A[16384,832] * W[1536,832]^T + bias   (z: side*2+dir, dir=1 gathers
// reversed A rows). 128x128x32 tiles, 8 warps of 32x64, mma.m16n8k8.tf32.
__device__ __forceinline__ unsigned f2tf(float x) {
    unsigned y;
    asm("cvt.rna.tf32.f32 %0, %1;" : "=r"(y) : "f"(x));
    return y;
}

#define TSTR 36

__global__ void __launch_bounds__(256, 2) k_gemm_tf(
    const float* __restrict__ wih, const float* __restrict__ bih,
    const int* __restrict__ len1, const int* __restrict__ len2)
{
    __shared__ unsigned As[128 * TSTR];
    __shared__ unsigned Bs[128 * TSTR];
    int z = blockIdx.z;
    int side = z >> 1, dir = z & 1;
    const float* A    = g_X[side];
    const float* W    = wih + (size_t)dir * G3 * DIN;
    const float* bias = bih + dir * G3;
    float* C = g_gi[z];
    const int* lens = side ? len2 : len1;

    int tid  = threadIdx.x;
    int m0   = blockIdx.y * 128, n0 = blockIdx.x * 128;
    int lr   = tid >> 1;
    int kq   = (tid & 1) * 16;
    int arow = m0 + lr;
    if (dir) {
        int b = arow >> 9, t = arow & 511;
        int Lb = lens[b];
        arow = (b << 9) + ((t < Lb) ? (Lb - 1 - t) : t);
    }
    const float* ap = A + (size_t)arow * DIN + kq;
    const float* bp = W + (size_t)(n0 + lr) * DIN + kq;

    int lane = tid & 31, warp = tid >> 5;
    int wr = warp & 3, wc = warp >> 2;
    int mbase = wr * 32, nbase = wc * 64;

    float c[2][8][4];
#pragma unroll
    for (int i = 0; i < 2; i++)
#pragma unroll
        for (int j = 0; j < 8; j++)
#pragma unroll
            for (int r = 0; r < 4; r++) c[i][j][r] = 0.f;

    float4 pa[4], pb[4];
#pragma unroll
    for (int i = 0; i < 4; i++) {
        pa[i] = *(const float4*)(ap + 4 * i);
        pb[i] = *(const float4*)(bp + 4 * i);
    }

    for (int k0 = 0; k0 < DIN; k0 += 32) {
        __syncthreads();
#pragma unroll
        for (int i = 0; i < 4; i++) {
            unsigned* d = &As[lr * TSTR + kq + 4 * i];
            d[0] = f2tf(pa[i].x); d[1] = f2tf(pa[i].y);
            d[2] = f2tf(pa[i].z); d[3] = f2tf(pa[i].w);
            unsigned* e = &Bs[lr * TSTR + kq + 4 * i];
            e[0] = f2tf(pb[i].x); e[1] = f2tf(pb[i].y);
            e[2] = f2tf(pb[i].z); e[3] = f2tf(pb[i].w);
        }
        __syncthreads();
        if (k0 + 32 < DIN) {
#pragma unroll
            for (int i = 0; i < 4; i++) {
                pa[i] = *(const float4*)(ap + k0 + 32 + 4 * i);
                pb[i] = *(const float4*)(bp + k0 + 32 + 4 * i);
            }
        }
#pragma unroll
        for (int kk = 0; kk < 32; kk += 8) {
            unsigned a[2][4];
#pragma unroll
            for (int i = 0; i < 2; i++) {
                int ao = (mbase + i * 16 + (lane >> 2)) * TSTR + kk + (lane & 3);
                a[i][0] = As[ao];
                a[i][1] = As[ao + 8 * TSTR];
                a[i][2] = As[ao + 4];
                a[i][3] = As[ao + 8 * TSTR + 4];
            }
#pragma unroll
            for (int j = 0; j < 8; j++) {
                int bo = (nbase + j * 8 + (lane >> 2)) * TSTR + kk + (lane & 3);
                unsigned b0 = Bs[bo], b1 = Bs[bo + 4];
#pragma unroll
                for (int i = 0; i < 2; i++) {
                    asm volatile(
                        "mma.sync.aligned.m16n8k8.row.col.f32.tf32.tf32.f32 "
                        "{%0,%1,%2,%3}, {%4,%5,%6,%7}, {%8,%9}, {%0,%1,%2,%3};"
                        : "+f"(c[i][j][0]), "+f"(c[i][j][1]),
                          "+f"(c[i][j][2]), "+f"(c[i][j][3])
                        : "r"(a[i][0]), "r"(a[i][1]), "r"(a[i][2]), "r"(a[i][3]),
                          "r"(b0), "r"(b1));
                }
            }
        }
    }
    int crow = lane >> 2, ccol = (lane & 3) * 2;
#pragma unroll
    for (int i = 0; i < 2; i++) {
#pragma unroll
        for (int j = 0; j < 8; j++) {
            int m = m0 + mbase + i * 16 + crow;
            int n = n0 + nbase + j * 8 + ccol;
            float b0v = bias[n], b1v = bias[n + 1];
            C[(size_t)m * G3 + n]           = c[i][j][0] + b0v;
            C[(size_t)m * G3 + n + 1]       = c[i][j][1] + b1v;
            C[(size_t)(m + 8) * G3 + n]     = c[i][j][2] + b0v;
            C[(size_t)(m + 8) * G3 + n + 1] = c[i][j][3] + b1v;
        }
    }
}

// ------------------------- fp32 SGEMM (sim): C = A * W^T -------------------------
#define BM 128
#define BN 128
#define BKG 8
#define SLD 132

__global__ void __launch_bounds__(256, 2) k_gemm(int M, int N, int K)
{
    __shared__ float As[BKG * SLD];
    __shared__ float Bs[BKG * SLD];
    int z = blockIdx.z;
    const float* A = g_enc[0] + (size_t)z * Lq * 1024;
    const float* W = g_enc[1] + (size_t)z * Lq * 1024;
    float* C = g_sim + (size_t)z * Lq * Lq;

    int tid  = threadIdx.x;
    int m0   = blockIdx.y * BM, n0 = blockIdx.x * BN;
    int lrow = tid >> 1;
    int kq   = (tid & 1) * 4;
    const float* ap = A + (size_t)(m0 + lrow) * K + kq;
    const float* bp = W + (size_t)(n0 + lrow) * K + kq;
    int tx = tid & 15, ty = tid >> 4;

    float acc[8][8];
#pragma unroll
    for (int i = 0; i < 8; i++)
#pragma unroll
        for (int j = 0; j < 8; j++) acc[i][j] = 0.f;

    for (int k0 = 0; k0 < K; k0 += BKG) {
        float4 av = *(const float4*)(ap + k0);
        float4 bv = *(const float4*)(bp + k0);
        __syncthreads();
        As[(kq + 0) * SLD + lrow] = av.x;
        As[(kq + 1) * SLD + lrow] = av.y;
        As[(kq + 2) * SLD + lrow] = av.z;
        As[(kq + 3) * SLD + lrow] = av.w;
        Bs[(kq + 0) * SLD + lrow] = bv.x;
        Bs[(kq + 1) * SLD + lrow] = bv.y;
        Bs[(kq + 2) * SLD + lrow] = bv.z;
        Bs[(kq + 3) * SLD + lrow] = bv.w;
        __syncthreads();
#pragma unroll
        for (int kk = 0; kk < BKG; kk++) {
            float a[8], b2[8];
#pragma unroll
            for (int i = 0; i < 8; i++) a[i]  = As[kk * SLD + ty + 16 * i];
#pragma unroll
            for (int j = 0; j < 8; j++) b2[j] = Bs[kk * SLD + tx + 16 * j];
#pragma unroll
            for (int i = 0; i < 8; i++)
#pragma unroll
                for (int j = 0; j < 8; j++) acc[i][j] += a[i] * b2[j];
        }
    }
#pragma unroll
    for (int i = 0; i < 8; i++) {
        int m = m0 + ty + 16 * i;
#pragma unroll
        for (int j = 0; j < 8; j++) {
            int n = n0 + tx + 16 * j;
            C[(size_t)m * N + n] = acc[i][j];
        }
    }
}

// ------------------------- persistent GRU scan -------------------------
#define GRU_SMEM ((48 * 512 + 512 * 33 + 48 * 33) * 4)

__global__ void __launch_bounds__(256, 1) k_gru(
    const float* __restrict__ whh, const float* __restrict__ bhh,
    const int* __restrict__ len1, const int* __restrict__ len2)
{
    extern __shared__ float sm[];
    float* Ws  = sm;                         // [48][512]
    float* hs  = sm + 48 * 512;              // [512][33]
    float* ghs = hs + 512 * 33;              // [48][33]

    int chain = blockIdx.x >> 5;
    int blk   = blockIdx.x & 31;
    int side  = chain >> 1, dir = chain & 1;
    int j0    = blk * 16;
    int tid   = threadIdx.x;
    const int* lens = side ? len2 : len1;
    const float* gi = g_gi[chain];
    float* enc = g_enc[side];

    for (int i = tid; i < 48 * 512; i += 256) {
        int rr = i >> 9, k = i & 511;
        int g = rr >> 4, u = rr & 15;
        Ws[rr * 512 + k] = whh[((size_t)dir * G3 + g * 512 + j0 + u) * 512 + k];
    }

    int w  = tid >> 5, l = tid & 31;
    int q  = l >> 2, ks = l & 3;
    int rr0 = w * 6;
    int b0  = q * 4;

    int gb  = tid & 31;
    int u0  = tid >> 5;
    int u1  = u0 + 8;
    int lenb = lens[gb];
    float bhr0 = bhh[dir * G3 +        j0 + u0];
    float bhz0 = bhh[dir * G3 +  512 + j0 + u0];
    float bhn0 = bhh[dir * G3 + 1024 + j0 + u0];
    float bhr1 = bhh[dir * G3 +        j0 + u1];
    float bhz1 = bhh[dir * G3 +  512 + j0 + u1];
    float bhn1 = bhh[dir * G3 + 1024 + j0 + u1];

    unsigned tgt = 0;
    for (int t = 0; t < Lq; ++t) {
        int p = t & 1;
        const float* hsrc = g_h[chain][p];
        for (int i = tid * 4; i < Hq * Bq; i += 1024) {
            float4 v = __ldcg((const float4*)(hsrc + i));
            int k = i >> 5, b = i & 31;
            float* d = hs + k * 33 + b;
            d[0] = v.x; d[1] = v.y; d[2] = v.z; d[3] = v.w;
        }
        __syncthreads();

        float acc[6][4];
#pragma unroll
        for (int y = 0; y < 6; y++)
#pragma unroll
            for (int x = 0; x < 4; x++) acc[y][x] = 0.f;
        {
            const float* hp = hs + ks * 33 + b0;
            const float* wp = Ws + rr0 * 512 + ks;
#pragma unroll 4
            for (int kk = 0; kk < 128; ++kk) {
                float h0 = hp[0], h1 = hp[1], h2 = hp[2], h3 = hp[3];
#pragma unroll
                for (int y = 0; y < 6; y++) {
                    float wv = wp[y * 512];
                    acc[y][0] += wv * h0;
                    acc[y][1] += wv * h1;
                    acc[y][2] += wv * h2;
                    acc[y][3] += wv * h3;
                }
                hp += 132; wp += 4;
            }
        }
#pragma unroll
        for (int y = 0; y < 6; y++)
#pragma unroll
            for (int x = 0; x < 4; x++) {
                float v = acc[y][x];
                v += __shfl_xor_sync(0xffffffffu, v, 1);
                v += __shfl_xor_sync(0xffffffffu, v, 2);
                acc[y][x] = v;
            }
        if (ks == 0) {
#pragma unroll
            for (int y = 0; y < 6; y++)
#pragma unroll
                for (int x = 0; x < 4; x++)
                    ghs[(rr0 + y) * 33 + b0 + x] = acc[y][x];
        }
        __syncthreads();

        bool valid = t < lenb;
        int tout = dir ? (valid ? lenb - 1 - t : t) : t;
        size_t tok = (size_t)((gb << 9) | t);
        size_t otok = (size_t)((gb << 9) | tout);
        const float* gp = gi + tok * G3 + j0;
        float* hdst = g_h[chain][p ^ 1];

        {
            float ir = gp[u0], iz = gp[512 + u0], inn = gp[1024 + u0];
            float hr = ghs[u0 * 33 + gb] + bhr0;
            float hz = ghs[(16 + u0) * 33 + gb] + bhz0;
            float hn = ghs[(32 + u0) * 33 + gb] + bhn0;
            float r  = 1.f / (1.f + expf(-(ir + hr)));
            float zz = 1.f / (1.f + expf(-(iz + hz)));
            float nn = tanhf(inn + r * hn);
            float hprev = hs[(j0 + u0) * 33 + gb];
            float hnew  = (1.f - zz) * nn + zz * hprev;
            hdst[((j0 + u0) << 5) + gb] = valid ? hnew : hprev;
            enc[otok * 1024 + (dir << 9) + j0 + u0] = valid ? hnew : 0.f;
        }
        {
            float ir = gp[u1], iz = gp[512 + u1], inn = gp[1024 + u1];
            float hr = ghs[u1 * 33 + gb] + bhr1;
            float hz = ghs[(16 + u1) * 33 + gb] + bhz1;
            float hn = ghs[(32 + u1) * 33 + gb] + bhn1;
            float r  = 1.f / (1.f + expf(-(ir + hr)));
            float zz = 1.f / (1.f + expf(-(iz + hz)));
            float nn = tanhf(inn + r * hn);
            float hprev = hs[(j0 + u1) * 33 + gb];
            float hnew  = (1.f - zz) * nn + zz * hprev;
            hdst[((j0 + u1) << 5) + gb] = valid ? hnew : hprev;
            enc[otok * 1024 + (dir << 9) + j0 + u1] = valid ? hnew : 0.f;
        }

        __threadfence();
        __syncthreads();
        tgt += 32;
        if (tid == 0) {
            atomicAdd(&g_ctr[chain], 1u);
            while (*(volatile unsigned*)&g_ctr[chain] < tgt) { }
        }
        __syncthreads();
    }
}

// ------------------------- row normalize enc -------------------------
__global__ void k_norm() {
    float* row = g_enc[blockIdx.y] + (size_t)blockIdx.x * 1024;
    int tid = threadIdx.x;
    float ss = 0.f;
    for (int i = tid; i < 1024; i += 128) { float v = row[i]; ss += v * v; }
    __shared__ float red[4];
    for (int o = 16; o; o >>= 1) ss += __shfl_down_sync(0xffffffffu, ss, o);
    if ((tid & 31) == 0) red[tid >> 5] = ss;
    __syncthreads();
    float tot = red[0] + red[1] + red[2] + red[3];
    float sc = tot > 0.f ? 1.f / sqrtf(tot) : 0.f;
    for (int i = tid; i < 1024; i += 128) row[i] *= sc;
}

// ------------------------- row / col max+argmax (first-index ties) -------------------------
__global__ void k_rowmax() {
    int row = blockIdx.x * 8 + (threadIdx.x >> 5);
    int l = threadIdx.x & 31;
    const float* s = g_sim + (size_t)row * Lq;
    float bv = -1e30f; int bi = 0;
    for (int j = l; j < Lq; j += 32) {
        float v = s[j];
        if (v > bv) { bv = v; bi = j; }
    }
    for (int o = 16; o; o >>= 1) {
        float ov = __shfl_down_sync(0xffffffffu, bv, o);
        int   oi = __shfl_down_sync(0xffffffffu, bi, o);
        if (ov > bv || (ov == bv && oi < bi)) { bv = ov; bi = oi; }
    }
    if (l == 0) {
        int i = row & 511;
        g_max1[row] = bv;
        g_rel1[row] = (float)(i - bi);
    }
}

__global__ void k_colmax() {
    int id = blockIdx.x * blockDim.x + threadIdx.x;
    int b = id >> 9, j = id & 511;
    const float* s = g_sim + ((size_t)b * Lq) * Lq + j;
    float bv = -1e30f; int bi = 0;
    for (int i = 0; i < Lq; ++i) {
        float v = s[(size_t)i * Lq];
        if (v > bv) { bv = v; bi = i; }
    }
    g_max2[id] = bv;
    g_rel2[id] = (float)(j - bi);
}

// ------------------------- conv branches + maxpool -------------------------
__global__ void k_head(const float* __restrict__ w2p, const float* __restrict__ w3p,
                       const float* __restrict__ w4p, const float* __restrict__ cb,
                       const float* __restrict__ bg, const float* __restrict__ bb,
                       const float* __restrict__ bm, const float* __restrict__ bvv)
{
    int b = blockIdx.x, br = blockIdx.y;
    __shared__ float x0[512], x1[512];
    const float* ms = br ? g_max2 : g_max1;
    const float* rl = br ? g_rel2 : g_rel1;
    for (int i = threadIdx.x; i < 512; i += 128) {
        x0[i] = ms[b * 512 + i];
        x1[i] = rl[b * 512 + i];
    }
    __syncthreads();
    int c = threadIdx.x;
    float* fout = g_feat + b * 768 + br * 384;
    const float* wp[3] = { w2p, w3p, w4p };
    const int kss[3] = { 2, 3, 4 };
    for (int ki = 0; ki < 3; ++ki) {
        int ks = kss[ki];
        float w0[4], w1[4];
        for (int kk = 0; kk < 4; kk++) {
            w0[kk] = kk < ks ? wp[ki][(c * 2 + 0) * ks + kk] : 0.f;
            w1[kk] = kk < ks ? wp[ki][(c * 2 + 1) * ks + kk] : 0.f;
        }
        float s  = bg[ki * 128 + c] / sqrtf(bvv[ki * 128 + c] + 1e-5f);
        float sh = bb[ki * 128 + c] - bm[ki * 128 + c] * s;
        float bias = cb[ki * 128 + c];
        float best = 0.f;
        for (int p = 0; p <= 512 - ks; ++p) {
            float acc = bias;
#pragma unroll
            for (int kk = 0; kk < 4; kk++)
                if (kk < ks) acc += w0[kk] * x0[p + kk] + w1[kk] * x1[p + kk];
            float y = fmaxf(acc * s + sh, 0.f);
            best = fmaxf(best, y);
        }
        fout[ki * 128 + c] = best;
    }
}

// ------------------------- FC + softmax -------------------------
__global__ void k_fc(const float* __restrict__ fcw, const float* __restrict__ fcb,
                     float* __restrict__ out)
{
    int id = threadIdx.x;
    int b = id >> 1, cls = id & 1;
    float acc = fcb[cls];
    const float* f = g_feat + b * 768;
    const float* wrow = fcw + cls * 768;
    for (int k = 0; k < 768; ++k) acc += f[k] * wrow[k];
    float other = __shfl_xor_sync(0xffffffffu, acc, 1);
    float m = fmaxf(acc, other);
    float e = expf(acc - m);
    float ssum = e + expf(other - m);
    out[id] = e / ssum;
}

// ------------------------- launch -------------------------
extern "C" void kernel_launch(void* const* d_in, const int* in_sizes, int n_in,
                              void* d_out, int out_size)
{
    const int* w1  = (const int*)d_in[0];
    const int* w2  = (const int*)d_in[1];
    const int* p1  = (const int*)d_in[2];
    const int* p2  = (const int*)d_in[3];
    const int* ln1 = (const int*)d_in[4];
    const int* ln2 = (const int*)d_in[5];
    const int* tb1 = (const int*)d_in[6];
    const int* te1 = (const int*)d_in[7];
    const int* tb2 = (const int*)d_in[8];
    const int* te2 = (const int*)d_in[9];
    const float* ew   = (const float*)d_in[10];
    const float* ep   = (const float*)d_in[11];
    const float* pe   = (const float*)d_in[12];
    const float* wih  = (const float*)d_in[13];
    const float* whh  = (const float*)d_in[14];
    const float* bih  = (const float*)d_in[15];
    const float* bhh  = (const float*)d_in[16];
    const float* cw0  = (const float*)d_in[17];
    const float* cw1  = (const float*)d_in[18];
    const float* cw2  = (const float*)d_in[19];
    const float* cb   = (const float*)d_in[20];
    const float* bg   = (const float*)d_in[21];
    const float* bb   = (const float*)d_in[22];
    const float* bm   = (const float*)d_in[23];
    const float* bv   = (const float*)d_in[24];
    const float* fcw  = (const float*)d_in[25];
    const float* fcb  = (const float*)d_in[26];
    float* out = (float*)d_out;

    cudaFuncSetAttribute(k_gru, cudaFuncAttributeMaxDynamicSharedMemorySize, GRU_SMEM);

    k_init<<<512, 256>>>();
    k_embed<<<dim3(BL, 2), 128>>>(w1, w2, p1, p2, tb1, te1, tb2, te2, ew, ep, pe);
    k_gemm_tf<<<dim3(G3 / 128, BL / 128, 4), 256>>>(wih, bih, ln1, ln2);
    k_gru<<<128, 256, GRU_SMEM>>>(whh, bhh, ln1, ln2);
    k_norm<<<dim3(BL, 2), 128>>>();
    k_gemm<<<dim3(Lq / BN, Lq / BM, Bq), 256>>>(Lq, Lq, 1024);
    k_rowmax<<<BL / 8, 256>>>();
    k_colmax<<<BL / 256, 256>>>();
    k_head<<<dim3(Bq, 2), 128>>>(cw0, cw1, cw2, cb, bg, bb, bm, bv);
    k_fc<<<1, 64>>>(fcw, fcb, out);
}

// round 4
// speedup vs baseline: 1.8339x; 1.3479x over previous
#include <cuda_runtime.h>
#include <math.h>

#define Bq   32
#define Lq   512
#define Hq   512
#define DIN  832
#define G3   1536
#define BL   (Bq*Lq)          // 16384

// ------------------------- scratch (device globals) -------------------------
__device__ __align__(16) float g_X[2][(size_t)BL * DIN];      // 109 MB
__device__ __align__(16) float g_gi[4][(size_t)BL * G3];      // 402 MB
__device__ __align__(16) float g_h[4][2][Bq * Hq];            // ping-pong hidden [b][k]
__device__ __align__(16) float g_enc[2][(size_t)BL * 1024];   // 134 MB
__device__ __align__(16) float g_sim[(size_t)Bq * Lq * Lq];   // 33.5 MB
__device__ __align__(16) float g_max1[BL], g_rel1[BL], g_max2[BL], g_rel2[BL];
__device__ __align__(16) float g_feat[Bq * 768];
__device__ unsigned g_ctr[4];

__device__ __forceinline__ unsigned f2tf(float x) {
    unsigned y;
    asm("cvt.rna.tf32.f32 %0, %1;" : "=r"(y) : "f"(x));
    return y;
}

// ------------------------- init (reset recurrence state) -------------------------
__global__ void k_init() {
    int i = blockIdx.x * blockDim.x + threadIdx.x;
    if (i < 4 * 2 * Hq * Bq) (&g_h[0][0][0])[i] = 0.f;
    if (i < 4) g_ctr[i] = 0u;
}

// ------------------------- embedding concat -------------------------
__global__ void k_embed(const int* __restrict__ w1, const int* __restrict__ w2,
                        const int* __restrict__ p1, const int* __restrict__ p2,
                        const int* __restrict__ tb1, const int* __restrict__ te1,
                        const int* __restrict__ tb2, const int* __restrict__ te2,
                        const float* __restrict__ ew, const float* __restrict__ ep,
                        const float* __restrict__ pe) {
    int tok  = blockIdx.x;
    int side = blockIdx.y;
    int t    = tok & (Lq - 1);
    const int* w  = side ? w2  : w1;
    const int* pp = side ? p2  : p1;
    const int* tb = side ? tb2 : tb1;
    const int* te = side ? te2 : te1;
    int wi = w[tok], pi = pp[tok], bi = tb[tok], ei = te[tok];
    float* dst = g_X[side] + (size_t)tok * DIN;
    const float* s0 = ew + (size_t)wi * 256;
    const float* s1 = ep + (size_t)pi * 256;
    for (int i = threadIdx.x; i < 256; i += 128) {
        dst[i]       = s0[i];
        dst[256 + i] = s1[i];
    }
    const float* q0 = pe + t * 64;
    const float* q1 = pe + bi * 64;
    const float* q2 = pe + ei * 64;
    const float* q3 = pe + (ei - t) * 64;
    const float* q4 = pe + (t - bi) * 64;
    for (int i = threadIdx.x; i < 64; i += 128) {
        dst[512 + i] = q0[i];
        dst[576 + i] = q1[i];
        dst[640 + i] = q2[i];
        dst[704 + i] = q3[i];
        dst[768 + i] = q4[i];
    }
}

// ------------------------- tf32 tensor-core GEMM for gi -------------------------
#define TSTR 36

__global__ void __launch_bounds__(256, 2) k_gemm_tf(
    const float* __restrict__ wih, const float* __restrict__ bih,
    const int* __restrict__ len1, const int* __restrict__ len2)
{
    __shared__ unsigned As[128 * TSTR];
    __shared__ unsigned Bs[128 * TSTR];
    int z = blockIdx.z;
    int side = z >> 1, dir = z & 1;
    const float* A    = g_X[side];
    const float* W    = wih + (size_t)dir * G3 * DIN;
    const float* bias = bih + dir * G3;
    float* C = g_gi[z];
    const int* lens = side ? len2 : len1;

    int tid  = threadIdx.x;
    int m0   = blockIdx.y * 128, n0 = blockIdx.x * 128;
    int lr   = tid >> 1;
    int kq   = (tid & 1) * 16;
    int arow = m0 + lr;
    if (dir) {
        int b = arow >> 9, t = arow & 511;
        int Lb = lens[b];
        arow = (b << 9) + ((t < Lb) ? (Lb - 1 - t) : t);
    }
    const float* ap = A + (size_t)arow * DIN + kq;
    const float* bp = W + (size_t)(n0 + lr) * DIN + kq;

    int lane = tid & 31, warp = tid >> 5;
    int wr = warp & 3, wc = warp >> 2;
    int mbase = wr * 32, nbase = wc * 64;

    float c[2][8][4];
#pragma unroll
    for (int i = 0; i < 2; i++)
#pragma unroll
        for (int j = 0; j < 8; j++)
#pragma unroll
            for (int r = 0; r < 4; r++) c[i][j][r] = 0.f;

    float4 pa[4], pb[4];
#pragma unroll
    for (int i = 0; i < 4; i++) {
        pa[i] = *(const float4*)(ap + 4 * i);
        pb[i] = *(const float4*)(bp + 4 * i);
    }

    for (int k0 = 0; k0 < DIN; k0 += 32) {
        __syncthreads();
#pragma unroll
        for (int i = 0; i < 4; i++) {
            unsigned* d = &As[lr * TSTR + kq + 4 * i];
            d[0] = f2tf(pa[i].x); d[1] = f2tf(pa[i].y);
            d[2] = f2tf(pa[i].z); d[3] = f2tf(pa[i].w);
            unsigned* e = &Bs[lr * TSTR + kq + 4 * i];
            e[0] = f2tf(pb[i].x); e[1] = f2tf(pb[i].y);
            e[2] = f2tf(pb[i].z); e[3] = f2tf(pb[i].w);
        }
        __syncthreads();
        if (k0 + 32 < DIN) {
#pragma unroll
            for (int i = 0; i < 4; i++) {
                pa[i] = *(const float4*)(ap + k0 + 32 + 4 * i);
                pb[i] = *(const float4*)(bp + k0 + 32 + 4 * i);
            }
        }
#pragma unroll
        for (int kk = 0; kk < 32; kk += 8) {
            unsigned a[2][4];
#pragma unroll
            for (int i = 0; i < 2; i++) {
                int ao = (mbase + i * 16 + (lane >> 2)) * TSTR + kk + (lane & 3);
                a[i][0] = As[ao];
                a[i][1] = As[ao + 8 * TSTR];
                a[i][2] = As[ao + 4];
                a[i][3] = As[ao + 8 * TSTR + 4];
            }
#pragma unroll
            for (int j = 0; j < 8; j++) {
                int bo = (nbase + j * 8 + (lane >> 2)) * TSTR + kk + (lane & 3);
                unsigned b0 = Bs[bo], b1 = Bs[bo + 4];
#pragma unroll
                for (int i = 0; i < 2; i++) {
                    asm volatile(
                        "mma.sync.aligned.m16n8k8.row.col.f32.tf32.tf32.f32 "
                        "{%0,%1,%2,%3}, {%4,%5,%6,%7}, {%8,%9}, {%0,%1,%2,%3};"
                        : "+f"(c[i][j][0]), "+f"(c[i][j][1]),
                          "+f"(c[i][j][2]), "+f"(c[i][j][3])
                        : "r"(a[i][0]), "r"(a[i][1]), "r"(a[i][2]), "r"(a[i][3]),
                          "r"(b0), "r"(b1));
                }
            }
        }
    }
    int crow = lane >> 2, ccol = (lane & 3) * 2;
#pragma unroll
    for (int i = 0; i < 2; i++) {
#pragma unroll
        for (int j = 0; j < 8; j++) {
            int m = m0 + mbase + i * 16 + crow;
            int n = n0 + nbase + j * 8 + ccol;
            float b0v = bias[n], b1v = bias[n + 1];
            C[(size_t)m * G3 + n]           = c[i][j][0] + b0v;
            C[(size_t)m * G3 + n + 1]       = c[i][j][1] + b1v;
            C[(size_t)(m + 8) * G3 + n]     = c[i][j][2] + b0v;
            C[(size_t)(m + 8) * G3 + n + 1] = c[i][j][3] + b1v;
        }
    }
}

// ------------------------- fp32 SGEMM (sim): C = A * W^T -------------------------
#define BM 128
#define BN 128
#define BKG 8
#define SLD 132

__global__ void __launch_bounds__(256, 2) k_gemm(int M, int N, int K)
{
    __shared__ float As[BKG * SLD];
    __shared__ float Bs[BKG * SLD];
    int z = blockIdx.z;
    const float* A = g_enc[0] + (size_t)z * Lq * 1024;
    const float* W = g_enc[1] + (size_t)z * Lq * 1024;
    float* C = g_sim + (size_t)z * Lq * Lq;

    int tid  = threadIdx.x;
    int m0   = blockIdx.y * BM, n0 = blockIdx.x * BN;
    int lrow = tid >> 1;
    int kq   = (tid & 1) * 4;
    const float* ap = A + (size_t)(m0 + lrow) * K + kq;
    const float* bp = W + (size_t)(n0 + lrow) * K + kq;
    int tx = tid & 15, ty = tid >> 4;

    float acc[8][8];
#pragma unroll
    for (int i = 0; i < 8; i++)
#pragma unroll
        for (int j = 0; j < 8; j++) acc[i][j] = 0.f;

    for (int k0 = 0; k0 < K; k0 += BKG) {
        float4 av = *(const float4*)(ap + k0);
        float4 bv = *(const float4*)(bp + k0);
        __syncthreads();
        As[(kq + 0) * SLD + lrow] = av.x;
        As[(kq + 1) * SLD + lrow] = av.y;
        As[(kq + 2) * SLD + lrow] = av.z;
        As[(kq + 3) * SLD + lrow] = av.w;
        Bs[(kq + 0) * SLD + lrow] = bv.x;
        Bs[(kq + 1) * SLD + lrow] = bv.y;
        Bs[(kq + 2) * SLD + lrow] = bv.z;
        Bs[(kq + 3) * SLD + lrow] = bv.w;
        __syncthreads();
#pragma unroll
        for (int kk = 0; kk < BKG; kk++) {
            float a[8], b2[8];
#pragma unroll
            for (int i = 0; i < 8; i++) a[i]  = As[kk * SLD + ty + 16 * i];
#pragma unroll
            for (int j = 0; j < 8; j++) b2[j] = Bs[kk * SLD + tx + 16 * j];
#pragma unroll
            for (int i = 0; i < 8; i++)
#pragma unroll
                for (int j = 0; j < 8; j++) acc[i][j] += a[i] * b2[j];
        }
    }
#pragma unroll
    for (int i = 0; i < 8; i++) {
        int m = m0 + ty + 16 * i;
#pragma unroll
        for (int j = 0; j < 8; j++) {
            int n = n0 + tx + 16 * j;
            C[(size_t)m * N + n] = acc[i][j];
        }
    }
}

// ------------------------- persistent GRU scan (tensor-core recurrence) -------------------------
// Per block per step: gh[48,32] = Ws[48,512] @ hT[32,512]^T via mma.m16n8k8.tf32.
// 8 warps K-split (64 k each) -> partials [8][48][33] -> reduce -> gates.
#define WSTR 516
#define GRU_SMEM ((48 * WSTR + 32 * WSTR + 8 * 48 * 33) * 4)

__global__ void __launch_bounds__(256, 1) k_gru(
    const float* __restrict__ whh, const float* __restrict__ bhh,
    const int* __restrict__ len1, const int* __restrict__ len2)
{
    extern __shared__ unsigned smu[];
    unsigned* Ws  = smu;                                 // [48][WSTR] tf32 bits
    float*    hT  = (float*)(smu + 48 * WSTR);           // [32][WSTR]
    float*    part = hT + 32 * WSTR;                     // [8][48*33]
    const unsigned* hTu = (const unsigned*)hT;

    int chain = blockIdx.x >> 5;
    int blk   = blockIdx.x & 31;
    int side  = chain >> 1, dir = chain & 1;
    int j0    = blk * 16;
    int tid   = threadIdx.x;
    int lane  = tid & 31, warp = tid >> 5;
    const int* lens = side ? len2 : len1;
    const float* gi = g_gi[chain];
    float* enc = g_enc[side];

    // load + convert Whh slice: rr = g*16+u <-> whh row dir*1536 + g*512 + j0 + u
    for (int i = tid; i < 48 * 512; i += 256) {
        int rr = i >> 9, k = i & 511;
        int g = rr >> 4, u = rr & 15;
        Ws[rr * WSTR + k] = f2tf(whh[((size_t)dir * G3 + g * 512 + j0 + u) * 512 + k]);
    }

    // gate-phase constants
    int gb  = tid & 31;
    int u0  = tid >> 5;
    int u1  = u0 + 8;
    int lenb = lens[gb];
    float bhr0 = bhh[dir * G3 +        j0 + u0];
    float bhz0 = bhh[dir * G3 +  512 + j0 + u0];
    float bhn0 = bhh[dir * G3 + 1024 + j0 + u0];
    float bhr1 = bhh[dir * G3 +        j0 + u1];
    float bhz1 = bhh[dir * G3 +  512 + j0 + u1];
    float bhn1 = bhh[dir * G3 + 1024 + j0 + u1];

    int kbase = warp * 64;
    unsigned tgt = 0;
    for (int t = 0; t < Lq; ++t) {
        int p = t & 1;
        // stage h: global [b][k] (already tf32 bits) -> smem hT[b][k]
        const float* hsrc = g_h[chain][p];
        for (int i = tid * 4; i < Bq * Hq; i += 1024) {
            float4 v = __ldcg((const float4*)(hsrc + i));
            int b = i >> 9, k = i & 511;
            *(float4*)(hT + b * WSTR + k) = v;
        }
        __syncthreads();

        // prefetch gi gate values (hide scattered-load latency behind mma)
        size_t tok = (size_t)((gb << 9) | t);
        const float* gp = gi + tok * G3 + j0;
        float ir0 = gp[u0], iz0 = gp[512 + u0], in0 = gp[1024 + u0];
        float ir1 = gp[u1], iz1 = gp[512 + u1], in1 = gp[1024 + u1];

        // mma: warp's K slice [kbase, kbase+64)
        float acc[3][4][4];
#pragma unroll
        for (int mt = 0; mt < 3; mt++)
#pragma unroll
            for (int nt = 0; nt < 4; nt++)
#pragma unroll
                for (int r = 0; r < 4; r++) acc[mt][nt][r] = 0.f;

#pragma unroll
        for (int ks8 = 0; ks8 < 64; ks8 += 8) {
            int k = kbase + ks8;
            unsigned a[3][4];
#pragma unroll
            for (int mt = 0; mt < 3; mt++) {
                int ao = (mt * 16 + (lane >> 2)) * WSTR + k + (lane & 3);
                a[mt][0] = Ws[ao];
                a[mt][1] = Ws[ao + 8 * WSTR];
                a[mt][2] = Ws[ao + 4];
                a[mt][3] = Ws[ao + 8 * WSTR + 4];
            }
            unsigned bfr[4][2];
#pragma unroll
            for (int nt = 0; nt < 4; nt++) {
                int bo = (nt * 8 + (lane >> 2)) * WSTR + k + (lane & 3);
                bfr[nt][0] = hTu[bo];
                bfr[nt][1] = hTu[bo + 4];
            }
#pragma unroll
            for (int mt = 0; mt < 3; mt++)
#pragma unroll
                for (int nt = 0; nt < 4; nt++) {
                    asm volatile(
                        "mma.sync.aligned.m16n8k8.row.col.f32.tf32.tf32.f32 "
                        "{%0,%1,%2,%3}, {%4,%5,%6,%7}, {%8,%9}, {%0,%1,%2,%3};"
                        : "+f"(acc[mt][nt][0]), "+f"(acc[mt][nt][1]),
                          "+f"(acc[mt][nt][2]), "+f"(acc[mt][nt][3])
                        : "r"(a[mt][0]), "r"(a[mt][1]), "r"(a[mt][2]), "r"(a[mt][3]),
                          "r"(bfr[nt][0]), "r"(bfr[nt][1]));
                }
        }
        // store partials
        {
            float* pw = part + warp * (48 * 33);
            int crow = lane >> 2, ccol = 2 * (lane & 3);
#pragma unroll
            for (int mt = 0; mt < 3; mt++)
#pragma unroll
                for (int nt = 0; nt < 4; nt++) {
                    int r0 = mt * 16 + crow;
                    int c0 = nt * 8 + ccol;
                    pw[r0 * 33 + c0]           = acc[mt][nt][0];
                    pw[r0 * 33 + c0 + 1]       = acc[mt][nt][1];
                    pw[(r0 + 8) * 33 + c0]     = acc[mt][nt][2];
                    pw[(r0 + 8) * 33 + c0 + 1] = acc[mt][nt][3];
                }
        }
        __syncthreads();

        // reduce 8 K-slices into part[0]
        for (int i = tid; i < 1536; i += 256) {
            int rr = i >> 5, b = i & 31;
            float s = 0.f;
#pragma unroll
            for (int w = 0; w < 8; w++) s += part[w * (48 * 33) + rr * 33 + b];
            part[rr * 33 + b] = s;
        }
        __syncthreads();

        // gates + state update (2 units per thread)
        bool valid = t < lenb;
        int tout = dir ? (valid ? lenb - 1 - t : t) : t;
        size_t otok = (size_t)((gb << 9) | tout);
        float* hdst = g_h[chain][p ^ 1];

        {
            float hr = part[u0 * 33 + gb] + bhr0;
            float hz = part[(16 + u0) * 33 + gb] + bhz0;
            float hn = part[(32 + u0) * 33 + gb] + bhn0;
            float r  = 1.f / (1.f + expf(-(ir0 + hr)));
            float zz = 1.f / (1.f + expf(-(iz0 + hz)));
            float nn = tanhf(in0 + r * hn);
            float hprev = hT[gb * WSTR + j0 + u0];
            float hnew  = (1.f - zz) * nn + zz * hprev;
            hdst[gb * 512 + j0 + u0] = valid ? __uint_as_float(f2tf(hnew)) : hprev;
            enc[otok * 1024 + (dir << 9) + j0 + u0] = valid ? hnew : 0.f;
        }
        {
            float hr = part[u1 * 33 + gb] + bhr1;
            float hz = part[(16 + u1) * 33 + gb] + bhz1;
            float hn = part[(32 + u1) * 33 + gb] + bhn1;
            float r  = 1.f / (1.f + expf(-(ir1 + hr)));
            float zz = 1.f / (1.f + expf(-(iz1 + hz)));
            float nn = tanhf(in1 + r * hn);
            float hprev = hT[gb * WSTR + j0 + u1];
            float hnew  = (1.f - zz) * nn + zz * hprev;
            hdst[gb * 512 + j0 + u1] = valid ? __uint_as_float(f2tf(hnew)) : hprev;
            enc[otok * 1024 + (dir << 9) + j0 + u1] = valid ? hnew : 0.f;
        }

        // device-scope step barrier (per chain)
        __threadfence();
        __syncthreads();
        tgt += 32;
        if (tid == 0) {
            atomicAdd(&g_ctr[chain], 1u);
            while (*(volatile unsigned*)&g_ctr[chain] < tgt) { }
        }
        __syncthreads();
    }
}

// ------------------------- row normalize enc -------------------------
__global__ void k_norm() {
    float* row = g_enc[blockIdx.y] + (size_t)blockIdx.x * 1024;
    int tid = threadIdx.x;
    float ss = 0.f;
    for (int i = tid; i < 1024; i += 128) { float v = row[i]; ss += v * v; }
    __shared__ float red[4];
    for (int o = 16; o; o >>= 1) ss += __shfl_down_sync(0xffffffffu, ss, o);
    if ((tid & 31) == 0) red[tid >> 5] = ss;
    __syncthreads();
    float tot = red[0] + red[1] + red[2] + red[3];
    float sc = tot > 0.f ? 1.f / sqrtf(tot) : 0.f;
    for (int i = tid; i < 1024; i += 128) row[i] *= sc;
}

// ------------------------- row / col max+argmax (first-index ties) -------------------------
__global__ void k_rowmax() {
    int row = blockIdx.x * 8 + (threadIdx.x >> 5);
    int l = threadIdx.x & 31;
    const float* s = g_sim + (size_t)row * Lq;
    float bv = -1e30f; int bi = 0;
    for (int j = l; j < Lq; j += 32) {
        float v = s[j];
        if (v > bv) { bv = v; bi = j; }
    }
    for (int o = 16; o; o >>= 1) {
        float ov = __shfl_down_sync(0xffffffffu, bv, o);
        int   oi = __shfl_down_sync(0xffffffffu, bi, o);
        if (ov > bv || (ov == bv && oi < bi)) { bv = ov; bi = oi; }
    }
    if (l == 0) {
        int i = row & 511;
        g_max1[row] = bv;
        g_rel1[row] = (float)(i - bi);
    }
}

__global__ void k_colmax() {
    int id = blockIdx.x * blockDim.x + threadIdx.x;
    int b = id >> 9, j = id & 511;
    const float* s = g_sim + ((size_t)b * Lq) * Lq + j;
    float bv = -1e30f; int bi = 0;
    for (int i = 0; i < Lq; ++i) {
        float v = s[(size_t)i * Lq];
        if (v > bv) { bv = v; bi = i; }
    }
    g_max2[id] = bv;
    g_rel2[id] = (float)(j - bi);
}

// ------------------------- conv branches + maxpool -------------------------
__global__ void k_head(const float* __restrict__ w2p, const float* __restrict__ w3p,
                       const float* __restrict__ w4p, const float* __restrict__ cb,
                       const float* __restrict__ bg, const float* __restrict__ bb,
                       const float* __restrict__ bm, const float* __restrict__ bvv)
{
    int b = blockIdx.x, br = blockIdx.y;
    __shared__ float x0[512], x1[512];
    const float* ms = br ? g_max2 : g_max1;
    const float* rl = br ? g_rel2 : g_rel1;
    for (int i = threadIdx.x; i < 512; i += 128) {
        x0[i] = ms[b * 512 + i];
        x1[i] = rl[b * 512 + i];
    }
    __syncthreads();
    int c = threadIdx.x;
    float* fout = g_feat + b * 768 + br * 384;
    const float* wp[3] = { w2p, w3p, w4p };
    const int kss[3] = { 2, 3, 4 };
    for (int ki = 0; ki < 3; ++ki) {
        int ks = kss[ki];
        float w0[4], w1[4];
        for (int kk = 0; kk < 4; kk++) {
            w0[kk] = kk < ks ? wp[ki][(c * 2 + 0) * ks + kk] : 0.f;
            w1[kk] = kk < ks ? wp[ki][(c * 2 + 1) * ks + kk] : 0.f;
        }
        float s  = bg[ki * 128 + c] / sqrtf(bvv[ki * 128 + c] + 1e-5f);
        float sh = bb[ki * 128 + c] - bm[ki * 128 + c] * s;
        float bias = cb[ki * 128 + c];
        float best = 0.f;
        for (int p = 0; p <= 512 - ks; ++p) {
            float acc = bias;
#pragma unroll
            for (int kk = 0; kk < 4; kk++)
                if (kk < ks) acc += w0[kk] * x0[p + kk] + w1[kk] * x1[p + kk];
            float y = fmaxf(acc * s + sh, 0.f);
            best = fmaxf(best, y);
        }
        fout[ki * 128 + c] = best;
    }
}

// ------------------------- FC + softmax -------------------------
__global__ void k_fc(const float* __restrict__ fcw, const float* __restrict__ fcb,
                     float* __restrict__ out)
{
    int id = threadIdx.x;
    int b = id >> 1, cls = id & 1;
    float acc = fcb[cls];
    const float* f = g_feat + b * 768;
    const float* wrow = fcw + cls * 768;
    for (int k = 0; k < 768; ++k) acc += f[k] * wrow[k];
    float other = __shfl_xor_sync(0xffffffffu, acc, 1);
    float m = fmaxf(acc, other);
    float e = expf(acc - m);
    float ssum = e + expf(other - m);
    out[id] = e / ssum;
}

// ------------------------- launch -------------------------
extern "C" void kernel_launch(void* const* d_in, const int* in_sizes, int n_in,
                              void* d_out, int out_size)
{
    const int* w1  = (const int*)d_in[0];
    const int* w2  = (const int*)d_in[1];
    const int* p1  = (const int*)d_in[2];
    const int* p2  = (const int*)d_in[3];
    const int* ln1 = (const int*)d_in[4];
    const int* ln2 = (const int*)d_in[5];
    const int* tb1 = (const int*)d_in[6];
    const int* te1 = (const int*)d_in[7];
    const int* tb2 = (const int*)d_in[8];
    const int* te2 = (const int*)d_in[9];
    const float* ew   = (const float*)d_in[10];
    const float* ep   = (const float*)d_in[11];
    const float* pe   = (const float*)d_in[12];
    const float* wih  = (const float*)d_in[13];
    const float* whh  = (const float*)d_in[14];
    const float* bih  = (const float*)d_in[15];
    const float* bhh  = (const float*)d_in[16];
    const float* cw0  = (const float*)d_in[17];
    const float* cw1  = (const float*)d_in[18];
    const float* cw2  = (const float*)d_in[19];
    const float* cb   = (const float*)d_in[20];
    const float* bg   = (const float*)d_in[21];
    const float* bb   = (const float*)d_in[22];
    const float* bm   = (const float*)d_in[23];
    const float* bv   = (const float*)d_in[24];
    const float* fcw  = (const float*)d_in[25];
    const float* fcb  = (const float*)d_in[26];
    float* out = (float*)d_out;

    cudaFuncSetAttribute(k_gru, cudaFuncAttributeMaxDynamicSharedMemorySize, GRU_SMEM);

    k_init<<<512, 256>>>();
    k_embed<<<dim3(BL, 2), 128>>>(w1, w2, p1, p2, tb1, te1, tb2, te2, ew, ep, pe);
    k_gemm_tf<<<dim3(G3 / 128, BL / 128, 4), 256>>>(wih, bih, ln1, ln2);
    k_gru<<<128, 256, GRU_SMEM>>>(whh, bhh, ln1, ln2);
    k_norm<<<dim3(BL, 2), 128>>>();
    k_gemm<<<dim3(Lq / BN, Lq / BM, Bq), 256>>>(Lq, Lq, 1024);
    k_rowmax<<<BL / 8, 256>>>();
    k_colmax<<<BL / 256, 256>>>();
    k_head<<<dim3(Bq, 2), 128>>>(cw0, cw1, cw2, cb, bg, bb, bm, bv);
    k_fc<<<1, 64>>>(fcw, fcb, out);
}

// round 5
// speedup vs baseline: 2.0472x; 1.1163x over previous
#include <cuda_runtime.h>
#include <math.h>

#define Bq   32
#define Lq   512
#define Hq   512
#define DIN  832
#define G3   1536
#define BL   (Bq*Lq)          // 16384

// ------------------------- scratch (device globals) -------------------------
__device__ __align__(16) float g_X[2][(size_t)BL * DIN];      // 109 MB
__device__ __align__(16) float g_gi[4][(size_t)BL * G3];      // 402 MB
__device__ __align__(16) float g_h[4][2][Bq * Hq];            // ping-pong hidden [b][k]
__device__ __align__(16) float g_enc[2][(size_t)BL * 1024];   // 134 MB
__device__ __align__(16) float g_sim[(size_t)Bq * Lq * Lq];   // 33.5 MB
__device__ __align__(16) float g_max1[BL], g_rel1[BL], g_max2[BL], g_rel2[BL];
__device__ __align__(16) float g_feat[Bq * 768];
__device__ unsigned g_ctr[4];

__device__ __forceinline__ unsigned f2tf(float x) {
    unsigned y;
    asm("cvt.rna.tf32.f32 %0, %1;" : "=r"(y) : "f"(x));
    return y;
}

__device__ __forceinline__ void cpa16(void* dst, const void* src) {
    unsigned d = (unsigned)__cvta_generic_to_shared(dst);
    asm volatile("cp.async.cg.shared.global [%0], [%1], 16;\n" :: "r"(d), "l"(src));
}

// ------------------------- init (reset recurrence state) -------------------------
__global__ void k_init() {
    int i = blockIdx.x * blockDim.x + threadIdx.x;
    if (i < 4 * 2 * Hq * Bq) (&g_h[0][0][0])[i] = 0.f;
    if (i < 4) g_ctr[i] = 0u;
}

// ------------------------- embedding concat -------------------------
__global__ void k_embed(const int* __restrict__ w1, const int* __restrict__ w2,
                        const int* __restrict__ p1, const int* __restrict__ p2,
                        const int* __restrict__ tb1, const int* __restrict__ te1,
                        const int* __restrict__ tb2, const int* __restrict__ te2,
                        const float* __restrict__ ew, const float* __restrict__ ep,
                        const float* __restrict__ pe) {
    int tok  = blockIdx.x;
    int side = blockIdx.y;
    int t    = tok & (Lq - 1);
    const int* w  = side ? w2  : w1;
    const int* pp = side ? p2  : p1;
    const int* tb = side ? tb2 : tb1;
    const int* te = side ? te2 : te1;
    int wi = w[tok], pi = pp[tok], bi = tb[tok], ei = te[tok];
    float* dst = g_X[side] + (size_t)tok * DIN;
    const float* s0 = ew + (size_t)wi * 256;
    const float* s1 = ep + (size_t)pi * 256;
    for (int i = threadIdx.x; i < 256; i += 128) {
        dst[i]       = s0[i];
        dst[256 + i] = s1[i];
    }
    const float* q0 = pe + t * 64;
    const float* q1 = pe + bi * 64;
    const float* q2 = pe + ei * 64;
    const float* q3 = pe + (ei - t) * 64;
    const float* q4 = pe + (t - bi) * 64;
    for (int i = threadIdx.x; i < 64; i += 128) {
        dst[512 + i] = q0[i];
        dst[576 + i] = q1[i];
        dst[640 + i] = q2[i];
        dst[704 + i] = q3[i];
        dst[768 + i] = q4[i];
    }
}

// ------------------------- unified tf32 tensor GEMM (cp.async 3-stage) -------------------------
// C[M,N] = A[M,K] * B[N,K]^T (+bias).  mode 0: gi (z=side*2+dir, reversed A gather for
// dir=1, bias). mode 1: sim (z=batch, A=enc1[z], B=enc2[z]).  fp32 fed raw to tf32 mma.
#define TSTR 36
#define NSTG 3
#define MMT_SLOT (2 * 128 * TSTR)
#define MMT_SMEM (NSTG * MMT_SLOT * 4)

__global__ void __launch_bounds__(256, 2) k_mmt(
    int mode, const float* __restrict__ wih, const float* __restrict__ bih,
    const int* __restrict__ len1, const int* __restrict__ len2)
{
    extern __shared__ float smd[];
    const float *A, *B, *bias = 0;
    float* C;
    int K, N, rev = 0;
    const int* lens = 0;
    int z = blockIdx.z;
    int m0 = blockIdx.y * 128, n0 = blockIdx.x * 128;
    if (mode == 0) {
        int side = z >> 1, dir = z & 1;
        A = g_X[side];
        B = wih + (size_t)dir * G3 * DIN;
        bias = bih + dir * G3;
        C = g_gi[z];
        K = DIN; N = G3;
        lens = side ? len2 : len1;
        rev = dir;
    } else {
        A = g_enc[0] + (size_t)z * Lq * 1024;
        B = g_enc[1] + (size_t)z * Lq * 1024;
        C = g_sim + (size_t)z * Lq * Lq;
        K = 1024; N = Lq;
    }
    int tid = threadIdx.x;

    // per-thread copy slots: A = 128 rows x 8 float4, 4 chunks/thread; same for B
    const float* asrc[4]; const float* bsrc[4]; int cdst[4];
#pragma unroll
    for (int i = 0; i < 4; i++) {
        int c = tid + 256 * i;
        int row = c >> 3, q = c & 7;
        int ar = m0 + row;
        if (rev) {
            int b = ar >> 9, t = ar & 511;
            int Lb = lens[b];
            ar = (b << 9) + ((t < Lb) ? (Lb - 1 - t) : t);
        }
        asrc[i] = A + (size_t)ar * K + q * 4;
        bsrc[i] = B + (size_t)(n0 + row) * K + q * 4;
        cdst[i] = row * TSTR + q * 4;
    }

    int KT = K / 32;
    // prologue: stages 0,1
#pragma unroll
    for (int s = 0; s < 2; s++) {
        float* As = smd + s * MMT_SLOT;
        float* Bs = As + 128 * TSTR;
#pragma unroll
        for (int i = 0; i < 4; i++) {
            cpa16(As + cdst[i], asrc[i] + s * 32);
            cpa16(Bs + cdst[i], bsrc[i] + s * 32);
        }
        asm volatile("cp.async.commit_group;\n");
    }

    int lane = tid & 31, warp = tid >> 5;
    int mbase = (warp & 3) * 32, nbase = (warp >> 2) * 64;

    float c[2][8][4];
#pragma unroll
    for (int i = 0; i < 2; i++)
#pragma unroll
        for (int j = 0; j < 8; j++)
#pragma unroll
            for (int r = 0; r < 4; r++) c[i][j][r] = 0.f;

    for (int kt = 0; kt < KT; kt++) {
        asm volatile("cp.async.wait_group 1;\n");
        __syncthreads();
        int slot = kt % NSTG;
        const unsigned* Au = (const unsigned*)(smd + slot * MMT_SLOT);
        const unsigned* Bu = Au + 128 * TSTR;
        // issue kt+2 into the slot just freed (kt-1)
        if (kt + 2 < KT) {
            int s2 = (kt + 2) % NSTG;
            float* As2 = smd + s2 * MMT_SLOT;
            float* Bs2 = As2 + 128 * TSTR;
#pragma unroll
            for (int i = 0; i < 4; i++) {
                cpa16(As2 + cdst[i], asrc[i] + (kt + 2) * 32);
                cpa16(Bs2 + cdst[i], bsrc[i] + (kt + 2) * 32);
            }
        }
        asm volatile("cp.async.commit_group;\n");

#pragma unroll
        for (int kk = 0; kk < 32; kk += 8) {
            unsigned a[2][4];
#pragma unroll
            for (int i = 0; i < 2; i++) {
                int ao = (mbase + i * 16 + (lane >> 2)) * TSTR + kk + (lane & 3);
                a[i][0] = Au[ao];
                a[i][1] = Au[ao + 8 * TSTR];
                a[i][2] = Au[ao + 4];
                a[i][3] = Au[ao + 8 * TSTR + 4];
            }
#pragma unroll
            for (int j = 0; j < 8; j++) {
                int bo = (nbase + j * 8 + (lane >> 2)) * TSTR + kk + (lane & 3);
                unsigned b0 = Bu[bo], b1 = Bu[bo + 4];
#pragma unroll
                for (int i = 0; i < 2; i++) {
                    asm volatile(
                        "mma.sync.aligned.m16n8k8.row.col.f32.tf32.tf32.f32 "
                        "{%0,%1,%2,%3}, {%4,%5,%6,%7}, {%8,%9}, {%0,%1,%2,%3};"
                        : "+f"(c[i][j][0]), "+f"(c[i][j][1]),
                          "+f"(c[i][j][2]), "+f"(c[i][j][3])
                        : "r"(a[i][0]), "r"(a[i][1]), "r"(a[i][2]), "r"(a[i][3]),
                          "r"(b0), "r"(b1));
                }
            }
        }
    }

    int crow = lane >> 2, ccol = (lane & 3) * 2;
#pragma unroll
    for (int i = 0; i < 2; i++) {
#pragma unroll
        for (int j = 0; j < 8; j++) {
            int m = m0 + mbase + i * 16 + crow;
            int n = n0 + nbase + j * 8 + ccol;
            float b0v = bias ? bias[n] : 0.f;
            float b1v = bias ? bias[n + 1] : 0.f;
            C[(size_t)m * N + n]           = c[i][j][0] + b0v;
            C[(size_t)m * N + n + 1]       = c[i][j][1] + b1v;
            C[(size_t)(m + 8) * N + n]     = c[i][j][2] + b0v;
            C[(size_t)(m + 8) * N + n + 1] = c[i][j][3] + b1v;
        }
    }
}

// ------------------------- persistent GRU scan (tensor-core recurrence) -------------------------
#define WSTR 516
#define GRU_SMEM ((48 * WSTR + 32 * WSTR + 8 * 48 * 33) * 4)

__global__ void __launch_bounds__(256, 1) k_gru(
    const float* __restrict__ whh, const float* __restrict__ bhh,
    const int* __restrict__ len1, const int* __restrict__ len2)
{
    extern __shared__ unsigned smu[];
    unsigned* Ws  = smu;                                 // [48][WSTR] tf32 bits
    float*    hT  = (float*)(smu + 48 * WSTR);           // [32][WSTR]
    float*    part = hT + 32 * WSTR;                     // [8][48*33]
    const unsigned* hTu = (const unsigned*)hT;

    int chain = blockIdx.x >> 5;
    int blk   = blockIdx.x & 31;
    int side  = chain >> 1, dir = chain & 1;
    int j0    = blk * 16;
    int tid   = threadIdx.x;
    int lane  = tid & 31, warp = tid >> 5;
    const int* lens = side ? len2 : len1;
    const float* gi = g_gi[chain];
    float* enc = g_enc[side];

    for (int i = tid; i < 48 * 512; i += 256) {
        int rr = i >> 9, k = i & 511;
        int g = rr >> 4, u = rr & 15;
        Ws[rr * WSTR + k] = f2tf(whh[((size_t)dir * G3 + g * 512 + j0 + u) * 512 + k]);
    }

    int gb  = tid & 31;
    int u0  = tid >> 5;
    int u1  = u0 + 8;
    int lenb = lens[gb];
    float bhr0 = bhh[dir * G3 +        j0 + u0];
    float bhz0 = bhh[dir * G3 +  512 + j0 + u0];
    float bhn0 = bhh[dir * G3 + 1024 + j0 + u0];
    float bhr1 = bhh[dir * G3 +        j0 + u1];
    float bhz1 = bhh[dir * G3 +  512 + j0 + u1];
    float bhn1 = bhh[dir * G3 + 1024 + j0 + u1];

    int kbase = warp * 64;
    unsigned tgt = 0;
    for (int t = 0; t < Lq; ++t) {
        int p = t & 1;
        const float* hsrc = g_h[chain][p];
        for (int i = tid * 4; i < Bq * Hq; i += 1024) {
            float4 v = __ldcg((const float4*)(hsrc + i));
            int b = i >> 9, k = i & 511;
            *(float4*)(hT + b * WSTR + k) = v;
        }
        __syncthreads();

        size_t tok = (size_t)((gb << 9) | t);
        const float* gp = gi + tok * G3 + j0;
        float ir0 = gp[u0], iz0 = gp[512 + u0], in0 = gp[1024 + u0];
        float ir1 = gp[u1], iz1 = gp[512 + u1], in1 = gp[1024 + u1];

        float acc[3][4][4];
#pragma unroll
        for (int mt = 0; mt < 3; mt++)
#pragma unroll
            for (int nt = 0; nt < 4; nt++)
#pragma unroll
                for (int r = 0; r < 4; r++) acc[mt][nt][r] = 0.f;

#pragma unroll
        for (int ks8 = 0; ks8 < 64; ks8 += 8) {
            int k = kbase + ks8;
            unsigned a[3][4];
#pragma unroll
            for (int mt = 0; mt < 3; mt++) {
                int ao = (mt * 16 + (lane >> 2)) * WSTR + k + (lane & 3);
                a[mt][0] = Ws[ao];
                a[mt][1] = Ws[ao + 8 * WSTR];
                a[mt][2] = Ws[ao + 4];
                a[mt][3] = Ws[ao + 8 * WSTR + 4];
            }
            unsigned bfr[4][2];
#pragma unroll
            for (int nt = 0; nt < 4; nt++) {
                int bo = (nt * 8 + (lane >> 2)) * WSTR + k + (lane & 3);
                bfr[nt][0] = hTu[bo];
                bfr[nt][1] = hTu[bo + 4];
            }
#pragma unroll
            for (int mt = 0; mt < 3; mt++)
#pragma unroll
                for (int nt = 0; nt < 4; nt++) {
                    asm volatile(
                        "mma.sync.aligned.m16n8k8.row.col.f32.tf32.tf32.f32 "
                        "{%0,%1,%2,%3}, {%4,%5,%6,%7}, {%8,%9}, {%0,%1,%2,%3};"
                        : "+f"(acc[mt][nt][0]), "+f"(acc[mt][nt][1]),
                          "+f"(acc[mt][nt][2]), "+f"(acc[mt][nt][3])
                        : "r"(a[mt][0]), "r"(a[mt][1]), "r"(a[mt][2]), "r"(a[mt][3]),
                          "r"(bfr[nt][0]), "r"(bfr[nt][1]));
                }
        }
        {
            float* pw = part + warp * (48 * 33);
            int crow = lane >> 2, ccol = 2 * (lane & 3);
#pragma unroll
            for (int mt = 0; mt < 3; mt++)
#pragma unroll
                for (int nt = 0; nt < 4; nt++) {
                    int r0 = mt * 16 + crow;
                    int c0 = nt * 8 + ccol;
                    pw[r0 * 33 + c0]           = acc[mt][nt][0];
                    pw[r0 * 33 + c0 + 1]       = acc[mt][nt][1];
                    pw[(r0 + 8) * 33 + c0]     = acc[mt][nt][2];
                    pw[(r0 + 8) * 33 + c0 + 1] = acc[mt][nt][3];
                }
        }
        __syncthreads();

        for (int i = tid; i < 1536; i += 256) {
            int rr = i >> 5, b = i & 31;
            float s = 0.f;
#pragma unroll
            for (int w = 0; w < 8; w++) s += part[w * (48 * 33) + rr * 33 + b];
            part[rr * 33 + b] = s;
        }
        __syncthreads();

        bool valid = t < lenb;
        int tout = dir ? (valid ? lenb - 1 - t : t) : t;
        size_t otok = (size_t)((gb << 9) | tout);
        float* hdst = g_h[chain][p ^ 1];

        {
            float hr = part[u0 * 33 + gb] + bhr0;
            float hz = part[(16 + u0) * 33 + gb] + bhz0;
            float hn = part[(32 + u0) * 33 + gb] + bhn0;
            float r  = 1.f / (1.f + expf(-(ir0 + hr)));
            float zz = 1.f / (1.f + expf(-(iz0 + hz)));
            float nn = tanhf(in0 + r * hn);
            float hprev = hT[gb * WSTR + j0 + u0];
            float hnew  = (1.f - zz) * nn + zz * hprev;
            hdst[gb * 512 + j0 + u0] = valid ? __uint_as_float(f2tf(hnew)) : hprev;
            enc[otok * 1024 + (dir << 9) + j0 + u0] = valid ? hnew : 0.f;
        }
        {
            float hr = part[u1 * 33 + gb] + bhr1;
            float hz = part[(16 + u1) * 33 + gb] + bhz1;
            float hn = part[(32 + u1) * 33 + gb] + bhn1;
            float r  = 1.f / (1.f + expf(-(ir1 + hr)));
            float zz = 1.f / (1.f + expf(-(iz1 + hz)));
            float nn = tanhf(in1 + r * hn);
            float hprev = hT[gb * WSTR + j0 + u1];
            float hnew  = (1.f - zz) * nn + zz * hprev;
            hdst[gb * 512 + j0 + u1] = valid ? __uint_as_float(f2tf(hnew)) : hprev;
            enc[otok * 1024 + (dir << 9) + j0 + u1] = valid ? hnew : 0.f;
        }

        __threadfence();
        __syncthreads();
        tgt += 32;
        if (tid == 0) {
            atomicAdd(&g_ctr[chain], 1u);
            while (*(volatile unsigned*)&g_ctr[chain] < tgt) { }
        }
        __syncthreads();
    }
}

// ------------------------- row normalize enc -------------------------
__global__ void k_norm() {
    float* row = g_enc[blockIdx.y] + (size_t)blockIdx.x * 1024;
    int tid = threadIdx.x;
    float ss = 0.f;
    for (int i = tid; i < 1024; i += 128) { float v = row[i]; ss += v * v; }
    __shared__ float red[4];
    for (int o = 16; o; o >>= 1) ss += __shfl_down_sync(0xffffffffu, ss, o);
    if ((tid & 31) == 0) red[tid >> 5] = ss;
    __syncthreads();
    float tot = red[0] + red[1] + red[2] + red[3];
    float sc = tot > 0.f ? 1.f / sqrtf(tot) : 0.f;
    for (int i = tid; i < 1024; i += 128) row[i] *= sc;
}

// ------------------------- row / col max+argmax (first-index ties) -------------------------
__global__ void k_rowmax() {
    int row = blockIdx.x * 8 + (threadIdx.x >> 5);
    int l = threadIdx.x & 31;
    const float* s = g_sim + (size_t)row * Lq;
    float bv = -1e30f; int bi = 0;
    for (int j = l; j < Lq; j += 32) {
        float v = s[j];
        if (v > bv) { bv = v; bi = j; }
    }
    for (int o = 16; o; o >>= 1) {
        float ov = __shfl_down_sync(0xffffffffu, bv, o);
        int   oi = __shfl_down_sync(0xffffffffu, bi, o);
        if (ov > bv || (ov == bv && oi < bi)) { bv = ov; bi = oi; }
    }
    if (l == 0) {
        int i = row & 511;
        g_max1[row] = bv;
        g_rel1[row] = (float)(i - bi);
    }
}

__global__ void k_colmax() {
    int id = blockIdx.x * blockDim.x + threadIdx.x;
    int b = id >> 9, j = id & 511;
    const float* s = g_sim + ((size_t)b * Lq) * Lq + j;
    float bv = -1e30f; int bi = 0;
    for (int i = 0; i < Lq; ++i) {
        float v = s[(size_t)i * Lq];
        if (v > bv) { bv = v; bi = i; }
    }
    g_max2[id] = bv;
    g_rel2[id] = (float)(j - bi);
}

// ------------------------- conv branches + maxpool -------------------------
__global__ void k_head(const float* __restrict__ w2p, const float* __restrict__ w3p,
                       const float* __restrict__ w4p, const float* __restrict__ cb,
                       const float* __restrict__ bg, const float* __restrict__ bb,
                       const float* __restrict__ bm, const float* __restrict__ bvv)
{
    int b = blockIdx.x, br = blockIdx.y;
    __shared__ float x0[512], x1[512];
    const float* ms = br ? g_max2 : g_max1;
    const float* rl = br ? g_rel2 : g_rel1;
    for (int i = threadIdx.x; i < 512; i += 128) {
        x0[i] = ms[b * 512 + i];
        x1[i] = rl[b * 512 + i];
    }
    __syncthreads();
    int c = threadIdx.x;
    float* fout = g_feat + b * 768 + br * 384;
    const float* wp[3] = { w2p, w3p, w4p };
    const int kss[3] = { 2, 3, 4 };
    for (int ki = 0; ki < 3; ++ki) {
        int ks = kss[ki];
        float w0[4], w1[4];
        for (int kk = 0; kk < 4; kk++) {
            w0[kk] = kk < ks ? wp[ki][(c * 2 + 0) * ks + kk] : 0.f;
            w1[kk] = kk < ks ? wp[ki][(c * 2 + 1) * ks + kk] : 0.f;
        }
        float s  = bg[ki * 128 + c] / sqrtf(bvv[ki * 128 + c] + 1e-5f);
        float sh = bb[ki * 128 + c] - bm[ki * 128 + c] * s;
        float bias = cb[ki * 128 + c];
        float best = 0.f;
        for (int p = 0; p <= 512 - ks; ++p) {
            float acc = bias;
#pragma unroll
            for (int kk = 0; kk < 4; kk++)
                if (kk < ks) acc += w0[kk] * x0[p + kk] + w1[kk] * x1[p + kk];
            float y = fmaxf(acc * s + sh, 0.f);
            best = fmaxf(best, y);
        }
        fout[ki * 128 + c] = best;
    }
}

// ------------------------- FC + softmax -------------------------
__global__ void k_fc(const float* __restrict__ fcw, const float* __restrict__ fcb,
                     float* __restrict__ out)
{
    int id = threadIdx.x;
    int b = id >> 1, cls = id & 1;
    float acc = fcb[cls];
    const float* f = g_feat + b * 768;
    const float* wrow = fcw + cls * 768;
    for (int k = 0; k < 768; ++k) acc += f[k] * wrow[k];
    float other = __shfl_xor_sync(0xffffffffu, acc, 1);
    float m = fmaxf(acc, other);
    float e = expf(acc - m);
    float ssum = e + expf(other - m);
    out[id] = e / ssum;
}

// ------------------------- launch -------------------------
extern "C" void kernel_launch(void* const* d_in, const int* in_sizes, int n_in,
                              void* d_out, int out_size)
{
    const int* w1  = (const int*)d_in[0];
    const int* w2  = (const int*)d_in[1];
    const int* p1  = (const int*)d_in[2];
    const int* p2  = (const int*)d_in[3];
    const int* ln1 = (const int*)d_in[4];
    const int* ln2 = (const int*)d_in[5];
    const int* tb1 = (const int*)d_in[6];
    const int* te1 = (const int*)d_in[7];
    const int* tb2 = (const int*)d_in[8];
    const int* te2 = (const int*)d_in[9];
    const float* ew   = (const float*)d_in[10];
    const float* ep   = (const float*)d_in[11];
    const float* pe   = (const float*)d_in[12];
    const float* wih  = (const float*)d_in[13];
    const float* whh  = (const float*)d_in[14];
    const float* bih  = (const float*)d_in[15];
    const float* bhh  = (const float*)d_in[16];
    const float* cw0  = (const float*)d_in[17];
    const float* cw1  = (const float*)d_in[18];
    const float* cw2  = (const float*)d_in[19];
    const float* cb   = (const float*)d_in[20];
    const float* bg   = (const float*)d_in[21];
    const float* bb   = (const float*)d_in[22];
    const float* bm   = (const float*)d_in[23];
    const float* bv   = (const float*)d_in[24];
    const float* fcw  = (const float*)d_in[25];
    const float* fcb  = (const float*)d_in[26];
    float* out = (float*)d_out;

    cudaFuncSetAttribute(k_mmt, cudaFuncAttributeMaxDynamicSharedMemorySize, MMT_SMEM);
    cudaFuncSetAttribute(k_gru, cudaFuncAttributeMaxDynamicSharedMemorySize, GRU_SMEM);

    k_init<<<512, 256>>>();
    k_embed<<<dim3(BL, 2), 128>>>(w1, w2, p1, p2, tb1, te1, tb2, te2, ew, ep, pe);
    k_mmt<<<dim3(G3 / 128, BL / 128, 4), 256, MMT_SMEM>>>(0, wih, bih, ln1, ln2);
    k_gru<<<128, 256, GRU_SMEM>>>(whh, bhh, ln1, ln2);
    k_norm<<<dim3(BL, 2), 128>>>();
    k_mmt<<<dim3(Lq / 128, Lq / 128, Bq), 256, MMT_SMEM>>>(1, 0, 0, 0, 0);
    k_rowmax<<<BL / 8, 256>>>();
    k_colmax<<<BL / 256, 256>>>();
    k_head<<<dim3(Bq, 2), 128>>>(cw0, cw1, cw2, cb, bg, bb, bm, bv);
    k_fc<<<1, 64>>>(fcw, fcb, out);
}